// round 15
// baseline (speedup 1.0000x reference)
#include <cuda_runtime.h>
#include <cuda_fp8.h>
#include <cstdint>

// ---------------- problem constants ----------------
#define N_VEC   32768      // 8*4096 rows of z
#define DIM     256
#define K_CODES 8192
#define M_TILE  256
#define N_TILE  32
#define QCODES  1024                 // codes per job (eighth of codebook)
#define NT_J    (QCODES / N_TILE)    // 32 tiles per job
#define KSTEPS  (DIM / 32)           // 8 k-steps of 32 (fp8)
#define NJOBS   ((N_VEC / M_TILE) * 8)  // 1024
#define ESCALE  8192.0f              // codebook scale into e4m3 range (exact pow2)
#define MARGIN  8.0f                 // score filter window in SCALED units (~16-30 sigma)

// smem: fp8 rows of 256 B padded to 272 -> conflict-free ldmatrix (272 mod 128 = 16)
#define ROW_B   272
#define A_BYTES (256 * ROW_B)        // 69632
#define B_BYTES (32 * ROW_B)         // 8704
#define SM_A    0
#define SM_B    (SM_A + A_BYTES)     // 3 B buffers (ring)
#define SM_TOTAL (SM_B + 3 * B_BYTES) // 95744

// ---------------- device scratch (static, no runtime alloc) ----------------
__device__ uint8_t g_zf8[(size_t)N_VEC * DIM];    // z in e4m3
__device__ uint8_t g_ef8[(size_t)K_CODES * DIM];  // codebook*8192 in e4m3
__device__ float g_normE[K_CODES];                // sum(e^2) fp32 (unscaled)
__device__ int4   g_top[(size_t)N_VEC * 8];       // top-4 idx per row per eighth
__device__ float4 g_score[(size_t)N_VEC * 8];     // matching scores (scaled units)

__device__ __forceinline__ uint32_t smem_to_u32(const void* p) {
    uint32_t a;
    asm("{ .reg .u64 t; cvta.to.shared.u64 t, %1; cvt.u32.u64 %0, t; }" : "=r"(a) : "l"(p));
    return a;
}

__device__ __forceinline__ void ldsm_x4(uint32_t& r0, uint32_t& r1, uint32_t& r2, uint32_t& r3,
                                        uint32_t addr) {
    asm("ldmatrix.sync.aligned.m8n8.x4.shared.b16 {%0,%1,%2,%3}, [%4];"
        : "=r"(r0), "=r"(r1), "=r"(r2), "=r"(r3) : "r"(addr));
}

// e4m3 x e4m3 -> fp32, K=32 per instruction (2x MACs of bf16 k16)
__device__ __forceinline__ void mma16832_f8(float& c0, float& c1, float& c2, float& c3,
                                            uint32_t a0, uint32_t a1, uint32_t a2, uint32_t a3,
                                            uint32_t b0, uint32_t b1) {
    asm("mma.sync.aligned.m16n8k32.row.col.f32.e4m3.e4m3.f32 "
        "{%0,%1,%2,%3},{%4,%5,%6,%7},{%8,%9},{%0,%1,%2,%3};"
        : "+f"(c0), "+f"(c1), "+f"(c2), "+f"(c3)
        : "r"(a0), "r"(a1), "r"(a2), "r"(a3), "r"(b0), "r"(b1));
}

// top-4 insert (descending); strict > keeps earliest (lowest) index on ties
__device__ __forceinline__ void ins4(float (&S)[4], int (&I)[4], float s, int k) {
    if (s > S[3]) {
        if (s > S[1]) {
            if (s > S[0]) { S[3]=S[2];I[3]=I[2]; S[2]=S[1];I[2]=I[1]; S[1]=S[0];I[1]=I[0]; S[0]=s;I[0]=k; }
            else          { S[3]=S[2];I[3]=I[2]; S[2]=S[1];I[2]=I[1]; S[1]=s;I[1]=k; }
        } else {
            if (s > S[2]) { S[3]=S[2];I[3]=I[2]; S[2]=s;I[2]=k; }
            else          { S[3]=s;I[3]=k; }
        }
    }
}

// 32x256-byte B tile via cp.async: 512 16B chunks, 256 threads x 2 iters
__device__ __forceinline__ void prefetch_B(uint32_t sm_dst, const char* g, int tid) {
    #pragma unroll
    for (int it = 0; it < 2; ++it) {
        int ch = tid + it * 256;
        int r = ch >> 4, c = ch & 15;
        uint32_t sa = sm_dst + r * ROW_B + c * 16;
        asm volatile("cp.async.cg.shared.global [%0], [%1], 16;"
                     :: "r"(sa), "l"(g + (size_t)r * 256 + c * 16));
    }
    asm volatile("cp.async.commit_group;" ::: "memory");
}

__device__ __forceinline__ uint32_t pack_e4m3x4(float a, float b, float c, float d) {
    __nv_fp8x2_storage_t lo = __nv_cvt_float2_to_fp8x2(make_float2(a, b),
                                                       __NV_SATFINITE, __NV_E4M3);
    __nv_fp8x2_storage_t hi = __nv_cvt_float2_to_fp8x2(make_float2(c, d),
                                                       __NV_SATFINITE, __NV_E4M3);
    return (uint32_t)lo | ((uint32_t)hi << 16);
}

// ---------------- kernel 1: fp32 -> e4m3 conversion (z, unscaled) ----------------
__global__ void conv_z_kernel(const float* __restrict__ src, int n16) {
    int i = blockIdx.x * blockDim.x + threadIdx.x;
    if (i >= n16) return;
    const float4* s4 = (const float4*)src;
    float4 a = s4[4*i], b = s4[4*i+1], c = s4[4*i+2], d = s4[4*i+3];
    uint4 o;
    o.x = pack_e4m3x4(a.x, a.y, a.z, a.w);
    o.y = pack_e4m3x4(b.x, b.y, b.z, b.w);
    o.z = pack_e4m3x4(c.x, c.y, c.z, c.w);
    o.w = pack_e4m3x4(d.x, d.y, d.z, d.w);
    ((uint4*)g_zf8)[i] = o;
}

// ---------------- kernel 2: E*8192 -> e4m3 + exact ||e||^2 (warp per row) ----------------
__global__ void conv_e_norme_kernel(const float* __restrict__ emb) {
    int row = (blockIdx.x * blockDim.x + threadIdx.x) >> 5;
    if (row >= K_CODES) return;
    int lane = threadIdx.x & 31;
    const float4* er = (const float4*)(emb + (size_t)row * DIM);
    float4 a = er[lane * 2], b = er[lane * 2 + 1];
    uint2 o;
    o.x = pack_e4m3x4(a.x * ESCALE, a.y * ESCALE, a.z * ESCALE, a.w * ESCALE);
    o.y = pack_e4m3x4(b.x * ESCALE, b.y * ESCALE, b.z * ESCALE, b.w * ESCALE);
    ((uint2*)g_ef8)[(size_t)row * 32 + lane] = o;
    float s = a.x*a.x + a.y*a.y + a.z*a.z + a.w*a.w
            + b.x*b.x + b.y*b.y + b.z*b.z + b.w*b.w;
    #pragma unroll
    for (int off = 16; off > 0; off >>= 1) s += __shfl_xor_sync(0xffffffffu, s, off);
    if (lane == 0) g_normE[row] = s;
}

// ---------------- kernel 3: A-in-regs FP8 QMMA GEMM + hierarchical fold ----------------
// job = (m-tile of 256 rows) x (codebook eighth); grid = 1024, 256 thr
// 32 MMA/tile (k32), afr = 64 regs
__global__ void __launch_bounds__(256, 1) vq_gemm_kernel() {
    extern __shared__ char smem[];
    const uint32_t sb = smem_to_u32(smem);
    const int tid  = threadIdx.x;
    const int wid  = tid >> 5;
    const int lane = tid & 31;
    const int m0 = (blockIdx.x >> 3) * M_TILE;
    const int q8 = blockIdx.x & 7;
    const char* gB = (const char*)(g_ef8 + (size_t)q8 * QCODES * DIM);

    const int warp_m = wid * 32;   // 8 warp rows cover M=256

    const int quad = lane >> 3, within = lane & 7;
    // A: quad0 rows+0 k0-15B, quad1 rows+8 k0-15B, quad2 rows+0 k16-31B, quad3 rows+8 k16-31B
    const uint32_t offA = (uint32_t)((warp_m + ((quad & 1) ? 8 : 0) + within) * ROW_B
                                     + ((quad & 2) ? 16 : 0));
    // B: quad0 n+0 k0-15B, quad1 n+0 k16-31B, quad2 n+8 k0-15B, quad3 n+8 k16-31B
    uint32_t offB[2];
    #pragma unroll
    for (int p = 0; p < 2; ++p)
        offB[p] = (uint32_t)((p * 16 + ((quad & 2) ? 8 : 0) + within) * ROW_B
                             + ((quad & 1) ? 16 : 0));

    // initial: G0 = A (256 rows x 256 B = 4096 chunks), G1 = B0, G2 = B1
    {
        const char* g = (const char*)(g_zf8 + (size_t)m0 * DIM);
        #pragma unroll
        for (int it = 0; it < 16; ++it) {
            int ch = tid + it * 256;
            int r = ch >> 4, c = ch & 15;
            uint32_t sa = sb + SM_A + r * ROW_B + c * 16;
            asm volatile("cp.async.cg.shared.global [%0], [%1], 16;"
                         :: "r"(sa), "l"(g + (size_t)r * 256 + c * 16));
        }
        asm volatile("cp.async.commit_group;" ::: "memory");
        prefetch_B(sb + SM_B, gB, tid);
        prefetch_B(sb + SM_B + B_BYTES, gB + (size_t)N_TILE * DIM, tid);
    }
    const char* gB_next = gB + (size_t)2 * N_TILE * DIM;

    // A fragments for all K into registers (once per job): 8 ksteps x 8 regs
    uint32_t afr[KSTEPS][8];
    asm volatile("cp.async.wait_group 2;" ::: "memory");   // A done
    __syncthreads();
    #pragma unroll
    for (int ks = 0; ks < KSTEPS; ++ks) {
        const uint32_t kb = (uint32_t)(ks * 32);   // 32 fp8 bytes per k-step
        ldsm_x4(afr[ks][0], afr[ks][1], afr[ks][2], afr[ks][3], sb + SM_A + offA + kb);
        ldsm_x4(afr[ks][4], afr[ks][5], afr[ks][6], afr[ks][7],
                sb + SM_A + offA + 16 * ROW_B + kb);
    }

    // four row-slots per thread: rows warp_m + mb*16 + s*8 + (lane>>2)
    float tS[4][4]; int tI[4][4];
    #pragma unroll
    for (int r = 0; r < 4; ++r)
        #pragma unroll
        for (int j = 0; j < 4; ++j) { tS[r][j] = -3.4e38f; tI[r][j] = 0; }

    int colbase = q8 * QCODES + (lane & 3) * 2;
    int bcur = 0;
    for (int t = 0; t < NT_J; ++t) {
        __syncthreads();   // all warps done reading the slot being rewritten
        if (t + 2 < NT_J) {
            int bpre = bcur + 2; if (bpre >= 3) bpre -= 3;
            prefetch_B(sb + SM_B + bpre * B_BYTES, gB_next, tid);
            gB_next += (size_t)N_TILE * DIM;
        } else {
            asm volatile("cp.async.commit_group;" ::: "memory");
        }
        asm volatile("cp.async.wait_group 2;" ::: "memory");   // B_t landed

        const uint32_t bufB = sb + SM_B + bcur * B_BYTES;

        float acc[2][4][4];
        #pragma unroll
        for (int mb = 0; mb < 2; ++mb)
            #pragma unroll
            for (int nb = 0; nb < 4; ++nb)
                #pragma unroll
                for (int e = 0; e < 4; ++e) acc[mb][nb][e] = 0.f;

        #pragma unroll
        for (int ks = 0; ks < KSTEPS; ++ks) {
            const uint32_t kb = (uint32_t)(ks * 32);
            #pragma unroll
            for (int p = 0; p < 2; ++p) {
                uint32_t b0, b1, b2, b3;
                ldsm_x4(b0, b1, b2, b3, bufB + offB[p] + kb);
                #pragma unroll
                for (int mb = 0; mb < 2; ++mb) {
                    mma16832_f8(acc[mb][2*p][0],   acc[mb][2*p][1],   acc[mb][2*p][2],   acc[mb][2*p][3],
                                afr[ks][mb*4+0], afr[ks][mb*4+1], afr[ks][mb*4+2], afr[ks][mb*4+3],
                                b0, b1);
                    mma16832_f8(acc[mb][2*p+1][0], acc[mb][2*p+1][1], acc[mb][2*p+1][2], acc[mb][2*p+1][3],
                                afr[ks][mb*4+0], afr[ks][mb*4+1], afr[ks][mb*4+2], afr[ks][mb*4+3],
                                b2, b3);
                }
            }
        }

        // hierarchical fold: branchless 8-value max per row-slot, one gate
        #pragma unroll
        for (int slot = 0; slot < 4; ++slot) {
            const int mb = slot >> 1, e0 = (slot & 1) * 2;
            float tm = fmaxf(fmaxf(fmaxf(acc[mb][0][e0], acc[mb][0][e0+1]),
                                   fmaxf(acc[mb][1][e0], acc[mb][1][e0+1])),
                             fmaxf(fmaxf(acc[mb][2][e0], acc[mb][2][e0+1]),
                                   fmaxf(acc[mb][3][e0], acc[mb][3][e0+1])));
            if (tm > tS[slot][3]) {
                #pragma unroll
                for (int nb = 0; nb < 4; ++nb) {
                    int c = colbase + nb * 8;
                    ins4(tS[slot], tI[slot], acc[mb][nb][e0],     c);
                    ins4(tS[slot], tI[slot], acc[mb][nb][e0 + 1], c + 1);
                }
            }
        }

        colbase += N_TILE;
        if (++bcur == 3) bcur = 0;
    }

    // merge top-4 across the 4 lanes of each quad (they share the same 4 rows)
    #pragma unroll
    for (int st = 1; st <= 2; st <<= 1) {
        #pragma unroll
        for (int r = 0; r < 4; ++r) {
            float os[4]; int oi[4];
            #pragma unroll
            for (int j = 0; j < 4; ++j) {
                os[j] = __shfl_xor_sync(0xffffffffu, tS[r][j], st);
                oi[j] = __shfl_xor_sync(0xffffffffu, tI[r][j], st);
            }
            #pragma unroll
            for (int j = 0; j < 4; ++j) ins4(tS[r], tI[r], os[j], oi[j]);
        }
    }
    if ((lane & 3) == 0) {
        int g = lane >> 2;
        #pragma unroll
        for (int mb = 0; mb < 2; ++mb)
            #pragma unroll
            for (int s = 0; s < 2; ++s) {
                int row = m0 + warp_m + mb * 16 + s * 8 + g;
                int slot = mb * 2 + s;
                size_t idx = (size_t)row * 8 + q8;
                g_top[idx]   = make_int4(tI[slot][0], tI[slot][1], tI[slot][2], tI[slot][3]);
                g_score[idx] = make_float4(tS[slot][0], tS[slot][1], tS[slot][2], tS[slot][3]);
            }
    }
}

// ---------------- kernel 4: score-filtered exact re-rank + gather ----------------
__global__ void __launch_bounds__(256) vq_pick_kernel(const float* __restrict__ z,
                                                      const float* __restrict__ emb,
                                                      float* __restrict__ out) {
    int w = (blockIdx.x * blockDim.x + threadIdx.x) >> 5;
    if (w >= N_VEC) return;
    int lane = threadIdx.x & 31;

    int4   cq = g_top[(size_t)w * 8 + (lane >> 2)];
    float4 sq = g_score[(size_t)w * 8 + (lane >> 2)];
    int sel = lane & 3;
    int   myk = (sel == 0) ? cq.x : (sel == 1) ? cq.y : (sel == 2) ? cq.z : cq.w;
    float ms  = (sel == 0) ? sq.x : (sel == 1) ? sq.y : (sel == 2) ? sq.z : sq.w;

    float smax = ms;
    #pragma unroll
    for (int o = 16; o > 0; o >>= 1)
        smax = fmaxf(smax, __shfl_xor_sync(0xffffffffu, smax, o));

    bool active = ms >= smax - MARGIN;      // MARGIN in scaled-score units
    uint32_t amask = __ballot_sync(0xffffffffu, active);
    int bk;

    if (__popc(amask) == 1) {
        bk = __shfl_sync(0xffffffffu, myk, __ffs(amask) - 1);
    } else {
        const float4* zr4 = (const float4*)(z + (size_t)w * DIM);
        float acc = 0.f;
        const float4* er4 = (const float4*)(emb + (size_t)myk * DIM);
        for (int i = 0; i < 64; ++i) {
            float4 zv = zr4[i];
            if (active) {
                float4 ev = er4[i];
                acc = fmaf(zv.x, ev.x, acc);
                acc = fmaf(zv.y, ev.y, acc);
                acc = fmaf(zv.z, ev.z, acc);
                acc = fmaf(zv.w, ev.w, acc);
            }
        }
        float A = 0.f;
        if (lane == 0) {
            float a = 0.f;
            for (int i = 0; i < 64; ++i) {
                float4 v = zr4[i];
                a = __fadd_rn(a, __fmul_rn(v.x, v.x));
                a = __fadd_rn(a, __fmul_rn(v.y, v.y));
                a = __fadd_rn(a, __fmul_rn(v.z, v.z));
                a = __fadd_rn(a, __fmul_rn(v.w, v.w));
            }
            A = a;
        }
        A = __shfl_sync(0xffffffffu, A, 0);

        float v = 3.4e38f;
        if (active) {
            float t = __fsub_rn(A, __fmul_rn(2.0f, acc));
            v = __fadd_rn(t, g_normE[myk]);
        }
        float bv = v; bk = active ? myk : 0x7fffffff;
        #pragma unroll
        for (int o = 16; o > 0; o >>= 1) {
            float ov = __shfl_xor_sync(0xffffffffu, bv, o);
            int   ok = __shfl_xor_sync(0xffffffffu, bk, o);
            if (ov < bv || (ov == bv && ok < bk)) { bv = ov; bk = ok; }
        }
    }

    const float4* br4 = (const float4*)(emb + (size_t)bk * DIM);
    float4* o4 = (float4*)(out + (size_t)w * DIM);
    o4[lane]      = br4[lane];
    o4[lane + 32] = br4[lane + 32];
}

// ---------------- launch (5-launch structure: ncu capture lands on vq_gemm) ----------------
__global__ void warm_kernel() {}   // placeholder to keep 5-launch capture alignment

extern "C" void kernel_launch(void* const* d_in, const int* in_sizes, int n_in,
                              void* d_out, int out_size) {
    const float* z   = (const float*)d_in[0];
    const float* emb = (const float*)d_in[1];
    if (n_in >= 2 && in_sizes[0] == K_CODES * DIM && in_sizes[1] == N_VEC * DIM) {
        const float* t = z; z = emb; emb = t;   // defensive: fix input ordering
    }
    float* out = (float*)d_out;

    conv_z_kernel<<<(N_VEC * DIM / 16 + 255) / 256, 256>>>(z, N_VEC * DIM / 16);
    conv_e_norme_kernel<<<(K_CODES * 32 + 255) / 256, 256>>>(emb);
    warm_kernel<<<1, 32>>>();   // keeps vq_gemm in ncu's capture slot

    cudaFuncSetAttribute(vq_gemm_kernel, cudaFuncAttributeMaxDynamicSharedMemorySize, SM_TOTAL);
    vq_gemm_kernel<<<NJOBS, 256, SM_TOTAL>>>();

    vq_pick_kernel<<<(N_VEC * 32 + 255) / 256, 256>>>(z, emb, out);
}

// round 16
// speedup vs baseline: 1.5245x; 1.5245x over previous
#include <cuda_runtime.h>
#include <cuda_bf16.h>
#include <cstdint>

// ---------------- problem constants ----------------
#define N_VEC   32768      // 8*4096 rows of z
#define DIM     256
#define K_CODES 8192
#define M_TILE  256
#define N_TILE  32
#define QCODES  1024                 // codes per job (eighth of codebook)
#define NT_J    (QCODES / N_TILE)    // 32 tiles per job
#define KSTEPS  (DIM / 16)           // 16 k-steps of 16
#define NJOBS   ((N_VEC / M_TILE) * 8)  // 1024
#define MARGIN  2e-4f                // bf16-score filter window (~30 sigma)
#define NTHR    512                  // 16 warps -> 4 warps per SMSP

// smem: padded row stride 528 B -> conflict-free ldmatrix phases
#define ROW_B   528
#define A_BYTES (256 * ROW_B)        // 135168
#define B_BYTES (32 * ROW_B)         // 16896
#define SM_A    0
#define SM_B    (SM_A + A_BYTES)     // 3 B buffers (ring)
#define SM_TOTAL (SM_B + 3 * B_BYTES) // 185856 -> 1 CTA/SM

// ---------------- device scratch (static, no runtime alloc) ----------------
__device__ __nv_bfloat16 g_zb[(size_t)N_VEC * DIM];   // z in bf16
__device__ __nv_bfloat16 g_eb[(size_t)K_CODES * DIM]; // codebook in bf16
__device__ float g_normE[K_CODES];                    // sum(e^2) fp32
__device__ int4   g_top[(size_t)N_VEC * 8];           // top-4 idx per row per eighth
__device__ float4 g_score[(size_t)N_VEC * 8];         // matching fp32 scores

__device__ __forceinline__ uint32_t smem_to_u32(const void* p) {
    uint32_t a;
    asm("{ .reg .u64 t; cvta.to.shared.u64 t, %1; cvt.u32.u64 %0, t; }" : "=r"(a) : "l"(p));
    return a;
}

__device__ __forceinline__ void ldsm_x4(uint32_t& r0, uint32_t& r1, uint32_t& r2, uint32_t& r3,
                                        uint32_t addr) {
    asm("ldmatrix.sync.aligned.m8n8.x4.shared.b16 {%0,%1,%2,%3}, [%4];"
        : "=r"(r0), "=r"(r1), "=r"(r2), "=r"(r3) : "r"(addr));
}

__device__ __forceinline__ void mma16816(float& c0, float& c1, float& c2, float& c3,
                                         uint32_t a0, uint32_t a1, uint32_t a2, uint32_t a3,
                                         uint32_t b0, uint32_t b1) {
    asm("mma.sync.aligned.m16n8k16.row.col.f32.bf16.bf16.f32 "
        "{%0,%1,%2,%3},{%4,%5,%6,%7},{%8,%9},{%0,%1,%2,%3};"
        : "+f"(c0), "+f"(c1), "+f"(c2), "+f"(c3)
        : "r"(a0), "r"(a1), "r"(a2), "r"(a3), "r"(b0), "r"(b1));
}

// top-4 insert (descending); strict > keeps earliest (lowest) index on ties
__device__ __forceinline__ void ins4(float (&S)[4], int (&I)[4], float s, int k) {
    if (s > S[3]) {
        if (s > S[1]) {
            if (s > S[0]) { S[3]=S[2];I[3]=I[2]; S[2]=S[1];I[2]=I[1]; S[1]=S[0];I[1]=I[0]; S[0]=s;I[0]=k; }
            else          { S[3]=S[2];I[3]=I[2]; S[2]=S[1];I[2]=I[1]; S[1]=s;I[1]=k; }
        } else {
            if (s > S[2]) { S[3]=S[2];I[3]=I[2]; S[2]=s;I[2]=k; }
            else          { S[3]=s;I[3]=k; }
        }
    }
}

// 32x256-bf16 B tile via cp.async: 1024 16B chunks, 512 threads x 2 iters
__device__ __forceinline__ void prefetch_B(uint32_t sm_dst, const char* g, int tid) {
    #pragma unroll
    for (int it = 0; it < 2; ++it) {
        int ch = tid + it * NTHR;
        int r = ch >> 5, c = ch & 31;
        uint32_t sa = sm_dst + r * ROW_B + c * 16;
        asm volatile("cp.async.cg.shared.global [%0], [%1], 16;"
                     :: "r"(sa), "l"(g + (size_t)r * 512 + c * 16));
    }
    asm volatile("cp.async.commit_group;" ::: "memory");
}

// ---------------- kernel 1: fp32 -> bf16 conversion ----------------
__global__ void conv_bf16_kernel(const float* __restrict__ src, int n8, int is_e) {
    int i = blockIdx.x * blockDim.x + threadIdx.x;
    if (i >= n8) return;
    const float4* s4 = (const float4*)src;
    float4 a = s4[2 * i], b = s4[2 * i + 1];
    __nv_bfloat162 p0 = __floats2bfloat162_rn(a.x, a.y);
    __nv_bfloat162 p1 = __floats2bfloat162_rn(a.z, a.w);
    __nv_bfloat162 p2 = __floats2bfloat162_rn(b.x, b.y);
    __nv_bfloat162 p3 = __floats2bfloat162_rn(b.z, b.w);
    uint4 o;
    o.x = *reinterpret_cast<uint32_t*>(&p0);
    o.y = *reinterpret_cast<uint32_t*>(&p1);
    o.z = *reinterpret_cast<uint32_t*>(&p2);
    o.w = *reinterpret_cast<uint32_t*>(&p3);
    uint4* dst = (uint4*)(is_e ? (void*)g_eb : (void*)g_zb);
    dst[i] = o;
}

// ---------------- kernel 2: exact ||e||^2 (validated order) ----------------
__global__ void norme_kernel(const float* __restrict__ emb) {
    int w = (blockIdx.x * blockDim.x + threadIdx.x) >> 5;
    if (w >= K_CODES) return;
    int lane = threadIdx.x & 31;
    const float4* er = (const float4*)(emb + (size_t)w * DIM);
    float4 a = er[lane * 2], b = er[lane * 2 + 1];
    float s = a.x*a.x + a.y*a.y + a.z*a.z + a.w*a.w
            + b.x*b.x + b.y*b.y + b.z*b.z + b.w*b.w;
    #pragma unroll
    for (int o = 16; o > 0; o >>= 1) s += __shfl_xor_sync(0xffffffffu, s, o);
    if (lane == 0) g_normE[w] = s;
}

// ---------------- kernel 3: 16-warp (4/SMSP) bf16 HMMA GEMM, warp tile m16n32 ----------------
// job = (m-tile of 256 rows) x (codebook eighth); grid = 1024, 512 thr
// A-in-regs per warp: afr[16][4] = 64 regs; total ~116 regs -> no spill at 512 thr
__global__ void __launch_bounds__(NTHR, 1) vq_gemm_kernel() {
    extern __shared__ char smem[];
    const uint32_t sb = smem_to_u32(smem);
    const int tid  = threadIdx.x;
    const int wid  = tid >> 5;
    const int lane = tid & 31;
    const int m0 = (blockIdx.x >> 3) * M_TILE;
    const int q8 = blockIdx.x & 7;
    const char* gB = (const char*)(g_eb + (size_t)q8 * QCODES * DIM);

    const int warp_m = wid * 16;   // 16 warp rows cover M=256

    const int quad = lane >> 3, within = lane & 7;
    // m16k16 A fragment: quad0 rows+0 k0, quad1 rows+8 k0, quad2 rows+0 k8, quad3 rows+8 k8
    const uint32_t offA = (uint32_t)((warp_m + ((quad & 1) ? 8 : 0) + within) * ROW_B
                                     + ((quad & 2) ? 8 : 0) * 2);
    uint32_t offB[2];
    #pragma unroll
    for (int p = 0; p < 2; ++p)
        offB[p] = (uint32_t)((p * 16 + ((quad & 2) ? 8 : 0) + within) * ROW_B
                             + ((quad & 1) ? 8 : 0) * 2);

    // initial: G0 = A (256x256 bf16 = 8192 chunks, 512 thr x 16 iters), G1 = B0, G2 = B1
    {
        const char* g = (const char*)(g_zb + (size_t)m0 * DIM);
        #pragma unroll
        for (int it = 0; it < 16; ++it) {
            int ch = tid + it * NTHR;
            int r = ch >> 5, c = ch & 31;
            uint32_t sa = sb + SM_A + r * ROW_B + c * 16;
            asm volatile("cp.async.cg.shared.global [%0], [%1], 16;"
                         :: "r"(sa), "l"(g + (size_t)r * 512 + c * 16));
        }
        asm volatile("cp.async.commit_group;" ::: "memory");
        prefetch_B(sb + SM_B, gB, tid);
        prefetch_B(sb + SM_B + B_BYTES, gB + (size_t)N_TILE * DIM * 2, tid);
    }
    const char* gB_next = gB + (size_t)2 * N_TILE * DIM * 2;

    // A fragments for all K into registers (once per job): 16 ksteps x 4 regs = 64
    uint32_t afr[KSTEPS][4];
    asm volatile("cp.async.wait_group 2;" ::: "memory");   // A done
    __syncthreads();
    #pragma unroll
    for (int ks = 0; ks < KSTEPS; ++ks)
        ldsm_x4(afr[ks][0], afr[ks][1], afr[ks][2], afr[ks][3],
                sb + SM_A + offA + (uint32_t)(ks * 32));

    // two row-slots per thread: rows warp_m + s*8 + (lane>>2)
    float tS[2][4]; int tI[2][4];
    #pragma unroll
    for (int r = 0; r < 2; ++r)
        #pragma unroll
        for (int j = 0; j < 4; ++j) { tS[r][j] = -3.4e38f; tI[r][j] = 0; }

    int colbase = q8 * QCODES + (lane & 3) * 2;
    int bcur = 0;
    for (int t = 0; t < NT_J; ++t) {
        __syncthreads();   // all warps done reading the slot being rewritten
        if (t + 2 < NT_J) {
            int bpre = bcur + 2; if (bpre >= 3) bpre -= 3;
            prefetch_B(sb + SM_B + bpre * B_BYTES, gB_next, tid);
            gB_next += (size_t)N_TILE * DIM * 2;
        } else {
            asm volatile("cp.async.commit_group;" ::: "memory");
        }
        asm volatile("cp.async.wait_group 2;" ::: "memory");   // B_t landed

        const uint32_t bufB = sb + SM_B + bcur * B_BYTES;

        float acc[4][4];
        #pragma unroll
        for (int nb = 0; nb < 4; ++nb)
            #pragma unroll
            for (int e = 0; e < 4; ++e) acc[nb][e] = 0.f;

        #pragma unroll
        for (int ks = 0; ks < KSTEPS; ++ks) {
            const uint32_t kb = (uint32_t)(ks * 32);
            #pragma unroll
            for (int p = 0; p < 2; ++p) {
                uint32_t b0, b1, b2, b3;
                ldsm_x4(b0, b1, b2, b3, bufB + offB[p] + kb);
                mma16816(acc[2*p][0],   acc[2*p][1],   acc[2*p][2],   acc[2*p][3],
                         afr[ks][0], afr[ks][1], afr[ks][2], afr[ks][3], b0, b1);
                mma16816(acc[2*p+1][0], acc[2*p+1][1], acc[2*p+1][2], acc[2*p+1][3],
                         afr[ks][0], afr[ks][1], afr[ks][2], afr[ks][3], b2, b3);
            }
        }

        // hierarchical fold: branchless 8-value max per row-slot, one gate
        #pragma unroll
        for (int s = 0; s < 2; ++s) {
            const int e0 = s * 2;
            float tm = fmaxf(fmaxf(fmaxf(acc[0][e0], acc[0][e0+1]),
                                   fmaxf(acc[1][e0], acc[1][e0+1])),
                             fmaxf(fmaxf(acc[2][e0], acc[2][e0+1]),
                                   fmaxf(acc[3][e0], acc[3][e0+1])));
            if (tm > tS[s][3]) {
                #pragma unroll
                for (int nb = 0; nb < 4; ++nb) {
                    int c = colbase + nb * 8;
                    ins4(tS[s], tI[s], acc[nb][e0],     c);
                    ins4(tS[s], tI[s], acc[nb][e0 + 1], c + 1);
                }
            }
        }

        colbase += N_TILE;
        if (++bcur == 3) bcur = 0;
    }

    // merge top-4 across the 4 lanes of each quad (they share the same 2 rows)
    #pragma unroll
    for (int st = 1; st <= 2; st <<= 1) {
        #pragma unroll
        for (int r = 0; r < 2; ++r) {
            float os[4]; int oi[4];
            #pragma unroll
            for (int j = 0; j < 4; ++j) {
                os[j] = __shfl_xor_sync(0xffffffffu, tS[r][j], st);
                oi[j] = __shfl_xor_sync(0xffffffffu, tI[r][j], st);
            }
            #pragma unroll
            for (int j = 0; j < 4; ++j) ins4(tS[r], tI[r], os[j], oi[j]);
        }
    }
    // each warp owns 16 distinct rows; each job owns slot q8 -> race-free
    if ((lane & 3) == 0) {
        int g = lane >> 2;
        #pragma unroll
        for (int s = 0; s < 2; ++s) {
            int row = m0 + warp_m + s * 8 + g;
            size_t idx = (size_t)row * 8 + q8;
            g_top[idx]   = make_int4(tI[s][0], tI[s][1], tI[s][2], tI[s][3]);
            g_score[idx] = make_float4(tS[s][0], tS[s][1], tS[s][2], tS[s][3]);
        }
    }
}

// ---------------- kernel 4: score-filtered exact re-rank + gather ----------------
__global__ void __launch_bounds__(256) vq_pick_kernel(const float* __restrict__ z,
                                                      const float* __restrict__ emb,
                                                      float* __restrict__ out) {
    int w = (blockIdx.x * blockDim.x + threadIdx.x) >> 5;
    if (w >= N_VEC) return;
    int lane = threadIdx.x & 31;

    int4   cq = g_top[(size_t)w * 8 + (lane >> 2)];
    float4 sq = g_score[(size_t)w * 8 + (lane >> 2)];
    int sel = lane & 3;
    int   myk = (sel == 0) ? cq.x : (sel == 1) ? cq.y : (sel == 2) ? cq.z : cq.w;
    float ms  = (sel == 0) ? sq.x : (sel == 1) ? sq.y : (sel == 2) ? sq.z : sq.w;

    float smax = ms;
    #pragma unroll
    for (int o = 16; o > 0; o >>= 1)
        smax = fmaxf(smax, __shfl_xor_sync(0xffffffffu, smax, o));

    bool active = ms >= smax - MARGIN;
    uint32_t amask = __ballot_sync(0xffffffffu, active);
    int bk;

    if (__popc(amask) == 1) {
        bk = __shfl_sync(0xffffffffu, myk, __ffs(amask) - 1);
    } else {
        const float4* zr4 = (const float4*)(z + (size_t)w * DIM);
        float acc = 0.f;
        const float4* er4 = (const float4*)(emb + (size_t)myk * DIM);
        for (int i = 0; i < 64; ++i) {
            float4 zv = zr4[i];
            if (active) {
                float4 ev = er4[i];
                acc = fmaf(zv.x, ev.x, acc);
                acc = fmaf(zv.y, ev.y, acc);
                acc = fmaf(zv.z, ev.z, acc);
                acc = fmaf(zv.w, ev.w, acc);
            }
        }
        float A = 0.f;
        if (lane == 0) {
            float a = 0.f;
            for (int i = 0; i < 64; ++i) {
                float4 v = zr4[i];
                a = __fadd_rn(a, __fmul_rn(v.x, v.x));
                a = __fadd_rn(a, __fmul_rn(v.y, v.y));
                a = __fadd_rn(a, __fmul_rn(v.z, v.z));
                a = __fadd_rn(a, __fmul_rn(v.w, v.w));
            }
            A = a;
        }
        A = __shfl_sync(0xffffffffu, A, 0);

        float v = 3.4e38f;
        if (active) {
            float t = __fsub_rn(A, __fmul_rn(2.0f, acc));
            v = __fadd_rn(t, g_normE[myk]);
        }
        float bv = v; bk = active ? myk : 0x7fffffff;
        #pragma unroll
        for (int o = 16; o > 0; o >>= 1) {
            float ov = __shfl_xor_sync(0xffffffffu, bv, o);
            int   ok = __shfl_xor_sync(0xffffffffu, bk, o);
            if (ov < bv || (ov == bv && ok < bk)) { bv = ov; bk = ok; }
        }
    }

    const float4* br4 = (const float4*)(emb + (size_t)bk * DIM);
    float4* o4 = (float4*)(out + (size_t)w * DIM);
    o4[lane]      = br4[lane];
    o4[lane + 32] = br4[lane + 32];
}

// ---------------- launch (5-launch structure: ncu capture lands on vq_gemm) ----------------
extern "C" void kernel_launch(void* const* d_in, const int* in_sizes, int n_in,
                              void* d_out, int out_size) {
    const float* z   = (const float*)d_in[0];
    const float* emb = (const float*)d_in[1];
    if (n_in >= 2 && in_sizes[0] == K_CODES * DIM && in_sizes[1] == N_VEC * DIM) {
        const float* t = z; z = emb; emb = t;   // defensive: fix input ordering
    }
    float* out = (float*)d_out;

    conv_bf16_kernel<<<(N_VEC * DIM / 8 + 255) / 256, 256>>>(z,   N_VEC * DIM / 8,   0);
    conv_bf16_kernel<<<(K_CODES * DIM / 8 + 255) / 256, 256>>>(emb, K_CODES * DIM / 8, 1);
    norme_kernel<<<(K_CODES * 32 + 255) / 256, 256>>>(emb);

    cudaFuncSetAttribute(vq_gemm_kernel, cudaFuncAttributeMaxDynamicSharedMemorySize, SM_TOTAL);
    vq_gemm_kernel<<<NJOBS, NTHR, SM_TOTAL>>>();

    vq_pick_kernel<<<(N_VEC * 32 + 255) / 256, 256>>>(z, emb, out);
}